// round 1
// baseline (speedup 1.0000x reference)
#include <cuda_runtime.h>
#include <cstdint>

// Problem constants (fixed by reference)
constexpr int HID = 128;
constexpr int N_NODES_MAX = 100000;
constexpr int N_EDGE_TYPES = 8;

// Scratch buffers (device globals: allocation-free)
__device__ float g_h[(size_t)N_NODES_MAX * HID];
__device__ float g_agg[(size_t)N_NODES_MAX * HID];
__device__ float g_t1[(size_t)N_NODES_MAX * HID];

// ---------------------------------------------------------------------------
// Zero-fill kernel (float4 grid-stride)
// ---------------------------------------------------------------------------
__global__ void zero_kernel(float4* __restrict__ p, int n4) {
    int i = blockIdx.x * blockDim.x + threadIdx.x;
    if (i < n4) p[i] = make_float4(0.f, 0.f, 0.f, 0.f);
}

// ---------------------------------------------------------------------------
// Edge message + scatter: agg[dst] += relu(h[src] + emb[etype])
// One warp per edge; each lane handles a float4 (4 feats).
// ---------------------------------------------------------------------------
__global__ __launch_bounds__(256) void scatter_kernel(
    const float* __restrict__ h,
    const int*   __restrict__ ei,    // [2, E]: src then dst
    const int*   __restrict__ et,    // [E]
    const float* __restrict__ emb,   // [8, 128]
    float*       __restrict__ agg,
    int E)
{
    __shared__ float s_emb[N_EDGE_TYPES * HID];
    for (int i = threadIdx.x; i < N_EDGE_TYPES * HID; i += 256)
        s_emb[i] = emb[i];
    __syncthreads();

    int e    = (blockIdx.x * 256 + threadIdx.x) >> 5;
    int lane = threadIdx.x & 31;
    if (e >= E) return;

    int s = ei[e];
    int d = ei[E + e];
    int t = et[e];

    float4 hv = *(const float4*)(h + (size_t)s * HID + lane * 4);
    float4 ev = *(const float4*)(s_emb + t * HID + lane * 4);
    float4 m;
    m.x = fmaxf(hv.x + ev.x, 0.f);
    m.y = fmaxf(hv.y + ev.y, 0.f);
    m.z = fmaxf(hv.z + ev.z, 0.f);
    m.w = fmaxf(hv.w + ev.w, 0.f);

    float* p = agg + (size_t)d * HID + lane * 4;
    asm volatile("red.global.add.v4.f32 [%0], {%1,%2,%3,%4};"
                 :: "l"(p), "f"(m.x), "f"(m.y), "f"(m.z), "f"(m.w)
                 : "memory");
}

// ---------------------------------------------------------------------------
// GEMM: out = relu( op(A) @ W + bias ), with optional combine
//   COMBINE: op(A)[i,k] = (1+eps)*A[i,k] + B[i,k]
// M x 128 @ 128 x 128. BM=128, BK=32, 256 threads, 8x8 micro-tile,
// stride-16 interleaved rows/cols for conflict-free smem access.
// ---------------------------------------------------------------------------
template<bool COMBINE>
__global__ __launch_bounds__(256) void gemm_relu_kernel(
    const float* __restrict__ A,
    const float* __restrict__ B,
    const float* __restrict__ eps,
    const float* __restrict__ W,
    const float* __restrict__ bias,
    float* __restrict__ out,
    int M)
{
    __shared__ float Ast[32][129];   // [k][row], padded to kill transpose conflicts
    __shared__ float Ws [32][132];   // [k][col], float4-aligned rows

    const int tid = threadIdx.x;
    const int tx  = tid & 15;        // col group
    const int ty  = tid >> 4;        // row group
    const int row0 = blockIdx.x * 128;

    const float e = COMBINE ? (1.0f + eps[0]) : 0.0f;

    float acc[8][8];
    #pragma unroll
    for (int m = 0; m < 8; m++)
        #pragma unroll
        for (int n = 0; n < 8; n++) acc[m][n] = 0.f;

    for (int kk = 0; kk < HID; kk += 32) {
        // --- load A tile (transposed into smem) ---
        #pragma unroll
        for (int i = 0; i < 4; i++) {
            int idx = tid + i * 256;     // 0..1023
            int r   = idx >> 3;          // 0..127
            int f4  = idx & 7;           // 0..7
            int gr  = row0 + r;
            float4 v = make_float4(0.f, 0.f, 0.f, 0.f);
            if (gr < M) {
                v = *(const float4*)(A + (size_t)gr * HID + kk + f4 * 4);
                if (COMBINE) {
                    float4 b = *(const float4*)(B + (size_t)gr * HID + kk + f4 * 4);
                    v.x = fmaf(e, v.x, b.x);
                    v.y = fmaf(e, v.y, b.y);
                    v.z = fmaf(e, v.z, b.z);
                    v.w = fmaf(e, v.w, b.w);
                }
            }
            Ast[f4 * 4 + 0][r] = v.x;
            Ast[f4 * 4 + 1][r] = v.y;
            Ast[f4 * 4 + 2][r] = v.z;
            Ast[f4 * 4 + 3][r] = v.w;
        }
        // --- load W tile ---
        #pragma unroll
        for (int i = 0; i < 4; i++) {
            int idx = tid + i * 256;     // 0..1023
            int r   = idx >> 5;          // 0..31
            int c4  = idx & 31;          // 0..31
            float4 v = *(const float4*)(W + (size_t)(kk + r) * HID + c4 * 4);
            *(float4*)&Ws[r][c4 * 4] = v;
        }
        __syncthreads();

        #pragma unroll
        for (int k = 0; k < 32; k++) {
            float a[8], w[8];
            #pragma unroll
            for (int m = 0; m < 8; m++) a[m] = Ast[k][ty + 16 * m];
            #pragma unroll
            for (int n = 0; n < 8; n++) w[n] = Ws[k][tx + 16 * n];
            #pragma unroll
            for (int m = 0; m < 8; m++)
                #pragma unroll
                for (int n = 0; n < 8; n++)
                    acc[m][n] = fmaf(a[m], w[n], acc[m][n]);
        }
        __syncthreads();
    }

    #pragma unroll
    for (int m = 0; m < 8; m++) {
        int gr = row0 + ty + 16 * m;
        if (gr >= M) continue;
        #pragma unroll
        for (int n = 0; n < 8; n++) {
            int c = tx + 16 * n;
            float v = acc[m][n] + bias[c];
            out[(size_t)gr * HID + c] = fmaxf(v, 0.f);
        }
    }
}

// ---------------------------------------------------------------------------
// Launch
// ---------------------------------------------------------------------------
extern "C" void kernel_launch(void* const* d_in, const int* in_sizes, int n_in,
                              void* d_out, int out_size)
{
    const float* x    = (const float*)d_in[0];
    const int*   ei   = (const int*)  d_in[1];
    const int*   ea   = (const int*)  d_in[2];
    const float* Wx   = (const float*)d_in[3];
    const float* bx   = (const float*)d_in[4];
    const float* emb  = (const float*)d_in[5];
    const float* eps1 = (const float*)d_in[6];
    const float* eps2 = (const float*)d_in[7];
    const float* W1a  = (const float*)d_in[8];
    const float* b1a  = (const float*)d_in[9];
    const float* W1b  = (const float*)d_in[10];
    const float* b1b  = (const float*)d_in[11];
    const float* W1c  = (const float*)d_in[12];
    const float* b1c  = (const float*)d_in[13];
    const float* W2a  = (const float*)d_in[14];
    const float* b2a  = (const float*)d_in[15];
    const float* W2b  = (const float*)d_in[16];
    const float* b2b  = (const float*)d_in[17];
    const float* W2c  = (const float*)d_in[18];
    const float* b2c  = (const float*)d_in[19];

    const int M = in_sizes[0] / HID;      // 100000
    const int E = in_sizes[1] / 2;        // 1600000
    float* out = (float*)d_out;

    float* h   = nullptr; cudaGetSymbolAddress((void**)&h,   g_h);
    float* agg = nullptr; cudaGetSymbolAddress((void**)&agg, g_agg);
    float* t1  = nullptr; cudaGetSymbolAddress((void**)&t1,  g_t1);

    const dim3 gemm_grid((M + 127) / 128);
    const int  n4        = M * HID / 4;
    const dim3 zero_grid((n4 + 255) / 256);
    const dim3 scat_grid((E + 7) / 8);

    // Encode: h = relu(x @ Wx + bx)
    gemm_relu_kernel<false><<<gemm_grid, 256>>>(x, nullptr, nullptr, Wx, bx, h, M);

    // ---- GINE layer 1 ----
    zero_kernel<<<zero_grid, 256>>>((float4*)agg, n4);
    scatter_kernel<<<scat_grid, 256>>>(h, ei, ea, emb, agg, E);
    gemm_relu_kernel<true ><<<gemm_grid, 256>>>(h, agg, eps1, W1a, b1a, t1, M);
    gemm_relu_kernel<false><<<gemm_grid, 256>>>(t1, nullptr, nullptr, W1b, b1b, agg, M);
    gemm_relu_kernel<false><<<gemm_grid, 256>>>(agg, nullptr, nullptr, W1c, b1c, h, M);

    // ---- GINE layer 2 ----
    zero_kernel<<<zero_grid, 256>>>((float4*)agg, n4);
    scatter_kernel<<<scat_grid, 256>>>(h, ei, ea, emb, agg, E);
    gemm_relu_kernel<true ><<<gemm_grid, 256>>>(h, agg, eps2, W2a, b2a, t1, M);
    gemm_relu_kernel<false><<<gemm_grid, 256>>>(t1, nullptr, nullptr, W2b, b2b, agg, M);
    gemm_relu_kernel<false><<<gemm_grid, 256>>>(agg, nullptr, nullptr, W2c, b2c, out, M);
}

// round 3
// speedup vs baseline: 1.3688x; 1.3688x over previous
#include <cuda_runtime.h>
#include <cuda_bf16.h>
#include <cstdint>

constexpr int HID = 128;
constexpr int N_NODES_MAX = 100000;
constexpr int N_EDGE_TYPES = 8;

// Scratch (device globals: allocation-free)
__device__ float g_h[(size_t)N_NODES_MAX * HID];
__device__ float g_agg[(size_t)N_NODES_MAX * HID];
__device__ float g_t1[(size_t)N_NODES_MAX * HID];
// Pre-split, fragment-ordered weight images: 7 weights x (hi,lo) x 16384 bf16
__device__ __nv_bfloat16 g_wimg[7 * 2 * 16384];

// ---------------------------------------------------------------------------
// mma.sync bf16 (plain compute_103-compatible tensor core path)
// ---------------------------------------------------------------------------
__device__ __forceinline__ void mma_bf16(float* c, const uint4& a,
                                         uint32_t b0, uint32_t b1) {
    asm volatile(
        "mma.sync.aligned.m16n8k16.row.col.f32.bf16.bf16.f32 "
        "{%0,%1,%2,%3}, {%4,%5,%6,%7}, {%8,%9}, {%0,%1,%2,%3};"
        : "+f"(c[0]), "+f"(c[1]), "+f"(c[2]), "+f"(c[3])
        : "r"(a.x), "r"(a.y), "r"(a.z), "r"(a.w), "r"(b0), "r"(b1));
}

// ---------------------------------------------------------------------------
// Prep: split W (fp32 [K,HID]) into bf16 hi/lo, stored in per-thread MMA
// fragment order for B (col-major K x N operand of m16n8k16).
// Element (k, n) goes to:
//   s=k>>4, half=(k&15)>>3, t=(k>>1)&3, e=k&1
//   g=n&7, lane=g*4+t, jt=n>>3, jp=jt>>1, which=jt&1, reg=which*2+half
//   byte = (s*8+jp)*512 + lane*16 + reg*4 + e*2
// ---------------------------------------------------------------------------
__global__ void prep_weight_kernel(const float* __restrict__ W,
                                   __nv_bfloat16* __restrict__ hi,
                                   __nv_bfloat16* __restrict__ lo) {
    int idx = blockIdx.x * blockDim.x + threadIdx.x;
    if (idx >= 16384) return;
    int k = idx >> 7;
    int n = idx & 127;
    float w = W[k * 128 + n];
    __nv_bfloat16 h = __float2bfloat16_rn(w);
    __nv_bfloat16 l = __float2bfloat16_rn(w - __bfloat162float(h));

    int s = k >> 4, half = (k & 15) >> 3, t = (k >> 1) & 3, e = k & 1;
    int g = n & 7, lane = g * 4 + t;
    int jt = n >> 3, jp = jt >> 1, which = jt & 1, reg = which * 2 + half;
    uint32_t off = (uint32_t)((s * 8 + jp) * 512 + lane * 16 + reg * 4 + e * 2);
    *(__nv_bfloat16*)((char*)hi + off) = h;
    *(__nv_bfloat16*)((char*)lo + off) = l;
}

// ---------------------------------------------------------------------------
// Zero-fill
// ---------------------------------------------------------------------------
__global__ void zero_kernel(float4* __restrict__ p, int n4) {
    int i = blockIdx.x * blockDim.x + threadIdx.x;
    if (i < n4) p[i] = make_float4(0.f, 0.f, 0.f, 0.f);
}

// ---------------------------------------------------------------------------
// Edge scatter: agg[dst] += relu(h[src] + emb[etype]); warp per edge, red.v4
// ---------------------------------------------------------------------------
__global__ __launch_bounds__(256) void scatter_kernel(
    const float* __restrict__ h, const int* __restrict__ ei,
    const int* __restrict__ et, const float* __restrict__ emb,
    float* __restrict__ agg, int E)
{
    __shared__ float s_emb[N_EDGE_TYPES * HID];
    for (int i = threadIdx.x; i < N_EDGE_TYPES * HID; i += 256) s_emb[i] = emb[i];
    __syncthreads();

    int e = (blockIdx.x * 256 + threadIdx.x) >> 5;
    int lane = threadIdx.x & 31;
    if (e >= E) return;
    int s = ei[e], d = ei[E + e], t = et[e];

    float4 hv = *(const float4*)(h + (size_t)s * HID + lane * 4);
    float4 ev = *(const float4*)(s_emb + t * HID + lane * 4);
    float4 m;
    m.x = fmaxf(hv.x + ev.x, 0.f); m.y = fmaxf(hv.y + ev.y, 0.f);
    m.z = fmaxf(hv.z + ev.z, 0.f); m.w = fmaxf(hv.w + ev.w, 0.f);
    float* p = agg + (size_t)d * HID + lane * 4;
    asm volatile("red.global.add.v4.f32 [%0], {%1,%2,%3,%4};"
                 :: "l"(p), "f"(m.x), "f"(m.y), "f"(m.z), "f"(m.w) : "memory");
}

// ---------------------------------------------------------------------------
// Tensor-core GEMM (mma.sync): out = relu( op(A) @ W + bias )
//   COMBINE: op(A) = (1+eps)*A + B
// Split-bf16 3-pass: Ah*Wh + Ah*Wl + Al*Wh, fp32 accumulate.
// CTA = 128 rows x 128 cols x K=128; 8 warps, warp tile 32x64.
// ---------------------------------------------------------------------------
constexpr int OFF_BIAS = 0;                 // 512 B
constexpr int OFF_AHI  = 512;               // 32 KB
constexpr int OFF_ALO  = OFF_AHI + 32768;
constexpr int OFF_BHI  = OFF_ALO + 32768;
constexpr int OFF_BLO  = OFF_BHI + 32768;
constexpr int SM_TOTAL = OFF_BLO + 32768;   // 131584 B

template<bool COMBINE>
__global__ __launch_bounds__(256) void gemm_mma_kernel(
    const float* __restrict__ A,
    const float* __restrict__ B,
    const float* __restrict__ eps,
    const __nv_bfloat16* __restrict__ w_hi,
    const __nv_bfloat16* __restrict__ w_lo,
    const float* __restrict__ bias,
    float* __restrict__ out,
    int M)
{
    extern __shared__ char smem[];
    const int tid = threadIdx.x;
    const int w   = tid >> 5;
    const int lid = tid & 31;
    const int row0 = blockIdx.x * 128;
    const float e = COMBINE ? (1.0f + eps[0]) : 0.0f;

    if (tid < 128) *(float*)(smem + OFF_BIAS + tid * 4) = bias[tid];

    // copy fragment-ordered weight images to smem
    {
        const uint4* hs = (const uint4*)w_hi;
        const uint4* ls = (const uint4*)w_lo;
        uint4* hd = (uint4*)(smem + OFF_BHI);
        uint4* ld = (uint4*)(smem + OFF_BLO);
        #pragma unroll
        for (int i = tid; i < 2048; i += 256) { hd[i] = hs[i]; ld[i] = ls[i]; }
    }

    // convert A tile -> bf16 hi/lo in A-fragment order
    // element (row, k): s=k>>4, half=(k&15)>>3, t=(k>>1)&3, g=row&7,
    //   rbit=(row>>3)&1, mt=row>>4, r=rbit+2*half
    //   byte = (s*8+mt)*512 + (g*4+t)*16 + r*4 (+2 for odd k)
    #pragma unroll
    for (int i = tid; i < 4096; i += 256) {
        int row = i >> 5;
        int q   = i & 31;
        int k0  = q * 4;
        int gr  = row0 + row;
        float4 v = make_float4(0.f, 0.f, 0.f, 0.f);
        if (gr < M) {
            v = *(const float4*)(A + (size_t)gr * HID + k0);
            if (COMBINE) {
                float4 b = *(const float4*)(B + (size_t)gr * HID + k0);
                v.x = fmaf(e, v.x, b.x); v.y = fmaf(e, v.y, b.y);
                v.z = fmaf(e, v.z, b.z); v.w = fmaf(e, v.w, b.w);
            }
        }
        __nv_bfloat16 hx = __float2bfloat16_rn(v.x), hy = __float2bfloat16_rn(v.y);
        __nv_bfloat16 hz = __float2bfloat16_rn(v.z), hw = __float2bfloat16_rn(v.w);
        __nv_bfloat162 h01(hx, hy), h23(hz, hw);
        __nv_bfloat162 l01(__float2bfloat16_rn(v.x - __bfloat162float(hx)),
                           __float2bfloat16_rn(v.y - __bfloat162float(hy)));
        __nv_bfloat162 l23(__float2bfloat16_rn(v.z - __bfloat162float(hz)),
                           __float2bfloat16_rn(v.w - __bfloat162float(hw)));

        int s    = k0 >> 4;
        int half = (k0 >> 3) & 1;
        int t    = (k0 >> 1) & 3;        // words at t and t+1
        int g    = row & 7;
        int rbit = (row >> 3) & 1;
        int mt   = row >> 4;
        int r    = rbit + 2 * half;
        uint32_t base = (uint32_t)((s * 8 + mt) * 512 + (g * 4 + t) * 16 + r * 4);
        *(uint32_t*)(smem + OFF_AHI + base)      = *(uint32_t*)&h01;
        *(uint32_t*)(smem + OFF_AHI + base + 16) = *(uint32_t*)&h23;
        *(uint32_t*)(smem + OFF_ALO + base)      = *(uint32_t*)&l01;
        *(uint32_t*)(smem + OFF_ALO + base + 16) = *(uint32_t*)&l23;
    }
    __syncthreads();

    // mainloop: warp tile 32x64. mt0=(w&3)*2, jp0=(w>>2)*4.
    const int mt0 = (w & 3) * 2;
    const int jp0 = (w >> 2) * 4;
    float acc[2][8][4];
    #pragma unroll
    for (int mi = 0; mi < 2; mi++)
        #pragma unroll
        for (int nt = 0; nt < 8; nt++)
            #pragma unroll
            for (int c = 0; c < 4; c++) acc[mi][nt][c] = 0.f;

    const uint4* sAh = (const uint4*)(smem + OFF_AHI);
    const uint4* sAl = (const uint4*)(smem + OFF_ALO);
    const uint4* sBh = (const uint4*)(smem + OFF_BHI);
    const uint4* sBl = (const uint4*)(smem + OFF_BLO);

    #pragma unroll
    for (int s = 0; s < 8; s++) {
        uint4 ah0 = sAh[(s * 8 + mt0) * 32 + lid];
        uint4 ah1 = sAh[(s * 8 + mt0 + 1) * 32 + lid];
        uint4 al0 = sAl[(s * 8 + mt0) * 32 + lid];
        uint4 al1 = sAl[(s * 8 + mt0 + 1) * 32 + lid];
        uint4 b[4];
        #pragma unroll
        for (int p = 0; p < 4; p++) b[p] = sBh[(s * 8 + jp0 + p) * 32 + lid];
        #pragma unroll
        for (int p = 0; p < 4; p++) {
            mma_bf16(acc[0][2 * p],     ah0, b[p].x, b[p].y);
            mma_bf16(acc[1][2 * p],     ah1, b[p].x, b[p].y);
            mma_bf16(acc[0][2 * p + 1], ah0, b[p].z, b[p].w);
            mma_bf16(acc[1][2 * p + 1], ah1, b[p].z, b[p].w);
            mma_bf16(acc[0][2 * p],     al0, b[p].x, b[p].y);
            mma_bf16(acc[1][2 * p],     al1, b[p].x, b[p].y);
            mma_bf16(acc[0][2 * p + 1], al0, b[p].z, b[p].w);
            mma_bf16(acc[1][2 * p + 1], al1, b[p].z, b[p].w);
        }
        #pragma unroll
        for (int p = 0; p < 4; p++) b[p] = sBl[(s * 8 + jp0 + p) * 32 + lid];
        #pragma unroll
        for (int p = 0; p < 4; p++) {
            mma_bf16(acc[0][2 * p],     ah0, b[p].x, b[p].y);
            mma_bf16(acc[1][2 * p],     ah1, b[p].x, b[p].y);
            mma_bf16(acc[0][2 * p + 1], ah0, b[p].z, b[p].w);
            mma_bf16(acc[1][2 * p + 1], ah1, b[p].z, b[p].w);
        }
    }

    // epilogue: bias + relu, direct float2 stores (32B sectors fully covered)
    const int g = lid >> 2, t = lid & 3;
    const float* bs = (const float*)(smem + OFF_BIAS);
    #pragma unroll
    for (int mi = 0; mi < 2; mi++) {
        #pragma unroll
        for (int nt = 0; nt < 8; nt++) {
            int col = (w >> 2) * 64 + nt * 8 + t * 2;
            float b0 = bs[col], b1 = bs[col + 1];
            int r0 = row0 + (w & 3) * 32 + mi * 16 + g;
            if (r0 < M) {
                float2 v0 = make_float2(fmaxf(acc[mi][nt][0] + b0, 0.f),
                                        fmaxf(acc[mi][nt][1] + b1, 0.f));
                *(float2*)(out + (size_t)r0 * HID + col) = v0;
            }
            int r1 = r0 + 8;
            if (r1 < M) {
                float2 v1 = make_float2(fmaxf(acc[mi][nt][2] + b0, 0.f),
                                        fmaxf(acc[mi][nt][3] + b1, 0.f));
                *(float2*)(out + (size_t)r1 * HID + col) = v1;
            }
        }
    }
}

// ---------------------------------------------------------------------------
// Launch
// ---------------------------------------------------------------------------
extern "C" void kernel_launch(void* const* d_in, const int* in_sizes, int n_in,
                              void* d_out, int out_size)
{
    const float* x    = (const float*)d_in[0];
    const int*   ei   = (const int*)  d_in[1];
    const int*   ea   = (const int*)  d_in[2];
    const float* Wx   = (const float*)d_in[3];
    const float* bx   = (const float*)d_in[4];
    const float* emb  = (const float*)d_in[5];
    const float* eps1 = (const float*)d_in[6];
    const float* eps2 = (const float*)d_in[7];
    const float* W1a  = (const float*)d_in[8];
    const float* b1a  = (const float*)d_in[9];
    const float* W1b  = (const float*)d_in[10];
    const float* b1b  = (const float*)d_in[11];
    const float* W1c  = (const float*)d_in[12];
    const float* b1c  = (const float*)d_in[13];
    const float* W2a  = (const float*)d_in[14];
    const float* b2a  = (const float*)d_in[15];
    const float* W2b  = (const float*)d_in[16];
    const float* b2b  = (const float*)d_in[17];
    const float* W2c  = (const float*)d_in[18];
    const float* b2c  = (const float*)d_in[19];

    const int M = in_sizes[0] / HID;   // 100000
    const int E = in_sizes[1] / 2;     // 1600000
    float* out = (float*)d_out;

    float* h   = nullptr; cudaGetSymbolAddress((void**)&h,   g_h);
    float* agg = nullptr; cudaGetSymbolAddress((void**)&agg, g_agg);
    float* t1  = nullptr; cudaGetSymbolAddress((void**)&t1,  g_t1);
    __nv_bfloat16* wimg = nullptr; cudaGetSymbolAddress((void**)&wimg, g_wimg);

    cudaFuncSetAttribute(gemm_mma_kernel<false>,
                         cudaFuncAttributeMaxDynamicSharedMemorySize, SM_TOTAL);
    cudaFuncSetAttribute(gemm_mma_kernel<true>,
                         cudaFuncAttributeMaxDynamicSharedMemorySize, SM_TOTAL);

    const float* Ws[7] = {Wx, W1a, W1b, W1c, W2a, W2b, W2c};
    for (int i = 0; i < 7; i++)
        prep_weight_kernel<<<64, 256>>>(Ws[i], wimg + (size_t)i * 32768,
                                        wimg + (size_t)i * 32768 + 16384);

    const dim3 gemm_grid((M + 127) / 128);
    const int  n4 = M * HID / 4;
    const dim3 zero_grid((n4 + 255) / 256);
    const dim3 scat_grid((E + 7) / 8);
    auto WH = [&](int i) { return wimg + (size_t)i * 32768; };
    auto WL = [&](int i) { return wimg + (size_t)i * 32768 + 16384; };

    // Encode
    gemm_mma_kernel<false><<<gemm_grid, 256, SM_TOTAL>>>(x, nullptr, nullptr, WH(0), WL(0), bx, h, M);

    // GINE layer 1
    zero_kernel<<<zero_grid, 256>>>((float4*)agg, n4);
    scatter_kernel<<<scat_grid, 256>>>(h, ei, ea, emb, agg, E);
    gemm_mma_kernel<true ><<<gemm_grid, 256, SM_TOTAL>>>(h, agg, eps1, WH(1), WL(1), b1a, t1, M);
    gemm_mma_kernel<false><<<gemm_grid, 256, SM_TOTAL>>>(t1, nullptr, nullptr, WH(2), WL(2), b1b, agg, M);
    gemm_mma_kernel<false><<<gemm_grid, 256, SM_TOTAL>>>(agg, nullptr, nullptr, WH(3), WL(3), b1c, h, M);

    // GINE layer 2
    zero_kernel<<<zero_grid, 256>>>((float4*)agg, n4);
    scatter_kernel<<<scat_grid, 256>>>(h, ei, ea, emb, agg, E);
    gemm_mma_kernel<true ><<<gemm_grid, 256, SM_TOTAL>>>(h, agg, eps2, WH(4), WL(4), b2a, t1, M);
    gemm_mma_kernel<false><<<gemm_grid, 256, SM_TOTAL>>>(t1, nullptr, nullptr, WH(5), WL(5), b2b, agg, M);
    gemm_mma_kernel<false><<<gemm_grid, 256, SM_TOTAL>>>(agg, nullptr, nullptr, WH(6), WL(6), b2c, out, M);
}

// round 4
// speedup vs baseline: 1.5590x; 1.1389x over previous
#include <cuda_runtime.h>
#include <cuda_bf16.h>
#include <cstdint>

constexpr int HID = 128;
constexpr int N_NODES_MAX = 100000;
constexpr int N_EDGE_TYPES = 8;

// Scratch (device globals: allocation-free)
__device__ float g_h[(size_t)N_NODES_MAX * HID];
__device__ float g_agg[(size_t)N_NODES_MAX * HID];
// Pre-split, fragment-ordered weight images: 7 weights x (hi,lo) x 16384 bf16
__device__ __nv_bfloat16 g_wimg[7 * 2 * 16384];

// ---------------------------------------------------------------------------
// helpers
// ---------------------------------------------------------------------------
__device__ __forceinline__ uint32_t smem_u32(const void* p) {
    uint32_t a;
    asm("{ .reg .u64 t; cvta.to.shared.u64 t, %1; cvt.u32.u64 %0, t; }" : "=r"(a) : "l"(p));
    return a;
}
__device__ __forceinline__ void cp_async16(uint32_t saddr, const void* g) {
    asm volatile("cp.async.cg.shared.global [%0], [%1], 16;" :: "r"(saddr), "l"(g) : "memory");
}
__device__ __forceinline__ void cp_commit() {
    asm volatile("cp.async.commit_group;" ::: "memory");
}
__device__ __forceinline__ void cp_wait0() {
    asm volatile("cp.async.wait_group 0;" ::: "memory");
}
__device__ __forceinline__ void mma_bf16(float* c, const uint4& a,
                                         uint32_t b0, uint32_t b1) {
    asm volatile(
        "mma.sync.aligned.m16n8k16.row.col.f32.bf16.bf16.f32 "
        "{%0,%1,%2,%3}, {%4,%5,%6,%7}, {%8,%9}, {%0,%1,%2,%3};"
        : "+f"(c[0]), "+f"(c[1]), "+f"(c[2]), "+f"(c[3])
        : "r"(a.x), "r"(a.y), "r"(a.z), "r"(a.w), "r"(b0), "r"(b1));
}
__device__ __forceinline__ void pack_hilo(float a, float b, uint32_t& hi, uint32_t& lo) {
    __nv_bfloat16 ha = __float2bfloat16_rn(a), hb = __float2bfloat16_rn(b);
    __nv_bfloat162 H(ha, hb);
    __nv_bfloat162 L(__float2bfloat16_rn(a - __bfloat162float(ha)),
                     __float2bfloat16_rn(b - __bfloat162float(hb)));
    hi = *(uint32_t*)&H;
    lo = *(uint32_t*)&L;
}

// smem layout (fused MLP kernel)
constexpr int OFF_BIAS = 0;                 // 3 x 512 B
constexpr int OFF_AHI  = 2048;
constexpr int OFF_ALO  = OFF_AHI + 32768;   // 34816
constexpr int OFF_BHI  = OFF_ALO + 32768;   // 67584
constexpr int OFF_BLO  = OFF_BHI + 32768;   // 100352
constexpr int SM_TOTAL = OFF_BLO + 32768;   // 133120

// ---------------------------------------------------------------------------
// Prep (single launch, blockIdx.y = weight index): split fp32 W into bf16
// hi/lo in per-thread MMA B-fragment order.
// ---------------------------------------------------------------------------
__global__ void prep_all_kernel(const float* W0, const float* W1, const float* W2,
                                const float* W3, const float* W4, const float* W5,
                                const float* W6, __nv_bfloat16* img) {
    const float* Ws[7] = {W0, W1, W2, W3, W4, W5, W6};
    int wi  = blockIdx.y;
    int idx = blockIdx.x * blockDim.x + threadIdx.x;
    if (idx >= 16384) return;
    int k = idx >> 7;
    int n = idx & 127;
    float w = Ws[wi][k * 128 + n];
    __nv_bfloat16 h = __float2bfloat16_rn(w);
    __nv_bfloat16 l = __float2bfloat16_rn(w - __bfloat162float(h));

    int s = k >> 4, half = (k & 15) >> 3, t = (k >> 1) & 3, e = k & 1;
    int g = n & 7, lane = g * 4 + t;
    int jt = n >> 3, jp = jt >> 1, which = jt & 1, reg = which * 2 + half;
    uint32_t off = (uint32_t)((s * 8 + jp) * 512 + lane * 16 + reg * 4 + e * 2);
    char* hi = (char*)(img + (size_t)wi * 32768);
    char* lo = hi + 32768;
    *(__nv_bfloat16*)(hi + off) = h;
    *(__nv_bfloat16*)(lo + off) = l;
}

// ---------------------------------------------------------------------------
// Zero-fill
// ---------------------------------------------------------------------------
__global__ void zero_kernel(float4* __restrict__ p, int n4) {
    int i = blockIdx.x * blockDim.x + threadIdx.x;
    if (i < n4) p[i] = make_float4(0.f, 0.f, 0.f, 0.f);
}

// ---------------------------------------------------------------------------
// Edge scatter: agg[dst] += relu(h[src] + emb[etype]); warp per edge, red.v4
// ---------------------------------------------------------------------------
__global__ __launch_bounds__(256) void scatter_kernel(
    const float* __restrict__ h, const int* __restrict__ ei,
    const int* __restrict__ et, const float* __restrict__ emb,
    float* __restrict__ agg, int E)
{
    __shared__ float s_emb[N_EDGE_TYPES * HID];
    for (int i = threadIdx.x; i < N_EDGE_TYPES * HID; i += 256) s_emb[i] = emb[i];
    __syncthreads();

    int e = (blockIdx.x * 256 + threadIdx.x) >> 5;
    int lane = threadIdx.x & 31;
    if (e >= E) return;
    int s = ei[e], d = ei[E + e], t = et[e];

    float4 hv = *(const float4*)(h + (size_t)s * HID + lane * 4);
    float4 ev = *(const float4*)(s_emb + t * HID + lane * 4);
    float4 m;
    m.x = fmaxf(hv.x + ev.x, 0.f); m.y = fmaxf(hv.y + ev.y, 0.f);
    m.z = fmaxf(hv.z + ev.z, 0.f); m.w = fmaxf(hv.w + ev.w, 0.f);
    float* p = agg + (size_t)d * HID + lane * 4;
    asm volatile("red.global.add.v4.f32 [%0], {%1,%2,%3,%4};"
                 :: "l"(p), "f"(m.x), "f"(m.y), "f"(m.z), "f"(m.w) : "memory");
}

// ---------------------------------------------------------------------------
// shared mainloop: acc += opA(128x128 split-bf16 frags) @ opB(...)
// warp tile 32x64; 24 MMAs per k-step (Ah*Bh, Ah*Bl, Al*Bh)
// ---------------------------------------------------------------------------
__device__ __forceinline__ void mma_mainloop(const char* smem, int w, int lid,
                                             float acc[2][8][4]) {
    const int mt0 = (w & 3) * 2;
    const int jp0 = (w >> 2) * 4;
    const uint4* sAh = (const uint4*)(smem + OFF_AHI);
    const uint4* sAl = (const uint4*)(smem + OFF_ALO);
    const uint4* sBh = (const uint4*)(smem + OFF_BHI);
    const uint4* sBl = (const uint4*)(smem + OFF_BLO);
    #pragma unroll
    for (int s = 0; s < 8; s++) {
        uint4 ah0 = sAh[(s * 8 + mt0) * 32 + lid];
        uint4 ah1 = sAh[(s * 8 + mt0 + 1) * 32 + lid];
        uint4 al0 = sAl[(s * 8 + mt0) * 32 + lid];
        uint4 al1 = sAl[(s * 8 + mt0 + 1) * 32 + lid];
        uint4 b[4];
        #pragma unroll
        for (int p = 0; p < 4; p++) b[p] = sBh[(s * 8 + jp0 + p) * 32 + lid];
        #pragma unroll
        for (int p = 0; p < 4; p++) {
            mma_bf16(acc[0][2 * p],     ah0, b[p].x, b[p].y);
            mma_bf16(acc[1][2 * p],     ah1, b[p].x, b[p].y);
            mma_bf16(acc[0][2 * p + 1], ah0, b[p].z, b[p].w);
            mma_bf16(acc[1][2 * p + 1], ah1, b[p].z, b[p].w);
            mma_bf16(acc[0][2 * p],     al0, b[p].x, b[p].y);
            mma_bf16(acc[1][2 * p],     al1, b[p].x, b[p].y);
            mma_bf16(acc[0][2 * p + 1], al0, b[p].z, b[p].w);
            mma_bf16(acc[1][2 * p + 1], al1, b[p].z, b[p].w);
        }
        #pragma unroll
        for (int p = 0; p < 4; p++) b[p] = sBl[(s * 8 + jp0 + p) * 32 + lid];
        #pragma unroll
        for (int p = 0; p < 4; p++) {
            mma_bf16(acc[0][2 * p],     ah0, b[p].x, b[p].y);
            mma_bf16(acc[1][2 * p],     ah1, b[p].x, b[p].y);
            mma_bf16(acc[0][2 * p + 1], ah0, b[p].z, b[p].w);
            mma_bf16(acc[1][2 * p + 1], ah1, b[p].z, b[p].w);
        }
    }
}

// async-load one weight image pair into B smem buffers
__device__ __forceinline__ void load_B_async(char* smem, const __nv_bfloat16* wimg,
                                             int tid) {
    uint32_t hB = smem_u32(smem + OFF_BHI);
    uint32_t lB = smem_u32(smem + OFF_BLO);
    const uint4* hs = (const uint4*)wimg;
    const uint4* ls = (const uint4*)(wimg + 16384);
    #pragma unroll
    for (int i = tid; i < 2048; i += 256) {
        cp_async16(hB + i * 16, hs + i);
        cp_async16(lB + i * 16, ls + i);
    }
    cp_commit();
}

// convert global fp32 tile (optionally combined) into A-frag hi/lo smem
template<bool COMBINE>
__device__ __forceinline__ void convert_A(char* smem, const float* A, const float* B,
                                          float e, int row0, int M, int tid) {
    #pragma unroll
    for (int i = tid; i < 4096; i += 256) {
        int row = i >> 5;
        int k0  = (i & 31) * 4;
        int gr  = row0 + row;
        float4 v = make_float4(0.f, 0.f, 0.f, 0.f);
        if (gr < M) {
            v = *(const float4*)(A + (size_t)gr * HID + k0);
            if (COMBINE) {
                float4 b = *(const float4*)(B + (size_t)gr * HID + k0);
                v.x = fmaf(e, v.x, b.x); v.y = fmaf(e, v.y, b.y);
                v.z = fmaf(e, v.z, b.z); v.w = fmaf(e, v.w, b.w);
            }
        }
        uint32_t h01, l01, h23, l23;
        pack_hilo(v.x, v.y, h01, l01);
        pack_hilo(v.z, v.w, h23, l23);
        int s    = k0 >> 4;
        int half = (k0 >> 3) & 1;
        int t    = (k0 >> 1) & 3;
        int g    = row & 7;
        int rbit = (row >> 3) & 1;
        int mt   = row >> 4;
        int r    = rbit + 2 * half;
        uint32_t base = (uint32_t)((s * 8 + mt) * 512 + (g * 4 + t) * 16 + r * 4);
        *(uint32_t*)(smem + OFF_AHI + base)      = h01;
        *(uint32_t*)(smem + OFF_AHI + base + 16) = h23;
        *(uint32_t*)(smem + OFF_ALO + base)      = l01;
        *(uint32_t*)(smem + OFF_ALO + base + 16) = l23;
    }
}

// ---------------------------------------------------------------------------
// Encode GEMM: out = relu(A @ W + bias)   (single stage)
// ---------------------------------------------------------------------------
__global__ __launch_bounds__(256) void gemm_enc_kernel(
    const float* __restrict__ A,
    const __nv_bfloat16* __restrict__ wimg,
    const float* __restrict__ bias,
    float* __restrict__ out, int M)
{
    extern __shared__ char smem[];
    const int tid = threadIdx.x, w = tid >> 5, lid = tid & 31;
    const int row0 = blockIdx.x * 128;

    load_B_async(smem, wimg, tid);
    if (tid < 128) *(float*)(smem + OFF_BIAS + tid * 4) = bias[tid];
    convert_A<false>(smem, A, nullptr, 0.f, row0, M, tid);
    cp_wait0();
    __syncthreads();

    float acc[2][8][4];
    #pragma unroll
    for (int mi = 0; mi < 2; mi++)
        #pragma unroll
        for (int nt = 0; nt < 8; nt++)
            #pragma unroll
            for (int c = 0; c < 4; c++) acc[mi][nt][c] = 0.f;

    mma_mainloop(smem, w, lid, acc);

    const int g = lid >> 2, tq = lid & 3;
    const float* bs = (const float*)(smem + OFF_BIAS);
    #pragma unroll
    for (int mi = 0; mi < 2; mi++)
        #pragma unroll
        for (int nt = 0; nt < 8; nt++) {
            int col = (w >> 2) * 64 + nt * 8 + tq * 2;
            float b0 = bs[col], b1 = bs[col + 1];
            int r0 = row0 + (w & 3) * 32 + mi * 16 + g;
            if (r0 < M)
                *(float2*)(out + (size_t)r0 * HID + col) =
                    make_float2(fmaxf(acc[mi][nt][0] + b0, 0.f),
                                fmaxf(acc[mi][nt][1] + b1, 0.f));
            int r1 = r0 + 8;
            if (r1 < M)
                *(float2*)(out + (size_t)r1 * HID + col) =
                    make_float2(fmaxf(acc[mi][nt][2] + b0, 0.f),
                                fmaxf(acc[mi][nt][3] + b1, 0.f));
        }
}

// ---------------------------------------------------------------------------
// Fused GINE MLP: out = relu( mlp( (1+eps)*h + agg ) ), 3 chained GEMMs.
// Intermediates stay on-chip: acc -> bias+relu -> split-bf16 A-frags (smem).
// ---------------------------------------------------------------------------
__global__ __launch_bounds__(256) void mlp3_kernel(
    const float* __restrict__ A,      // h
    const float* __restrict__ B,      // agg
    const float* __restrict__ eps,
    const __nv_bfloat16* __restrict__ wa,
    const __nv_bfloat16* __restrict__ wb,
    const __nv_bfloat16* __restrict__ wc,
    const float* __restrict__ ba,
    const float* __restrict__ bb,
    const float* __restrict__ bc,
    float* __restrict__ out, int M)
{
    extern __shared__ char smem[];
    const int tid = threadIdx.x, w = tid >> 5, lid = tid & 31;
    const int row0 = blockIdx.x * 128;
    const float e = 1.0f + eps[0];

    load_B_async(smem, wa, tid);
    if (tid < 128) {
        *(float*)(smem + OFF_BIAS +        tid * 4) = ba[tid];
        *(float*)(smem + OFF_BIAS +  512 + tid * 4) = bb[tid];
        *(float*)(smem + OFF_BIAS + 1024 + tid * 4) = bc[tid];
    }
    convert_A<true>(smem, A, B, e, row0, M, tid);
    cp_wait0();
    __syncthreads();

    float acc[2][8][4];
    const int g = lid >> 2, tq = lid & 3;
    const __nv_bfloat16* next_w[2] = {wb, wc};

    #pragma unroll
    for (int st = 0; st < 3; st++) {
        #pragma unroll
        for (int mi = 0; mi < 2; mi++)
            #pragma unroll
            for (int nt = 0; nt < 8; nt++)
                #pragma unroll
                for (int c = 0; c < 4; c++) acc[mi][nt][c] = 0.f;

        mma_mainloop(smem, w, lid, acc);
        __syncthreads();   // all warps done reading A & B frags

        const float* bs = (const float*)(smem + OFF_BIAS + st * 512);

        if (st < 2) {
            load_B_async(smem, next_w[st], tid);   // overlaps with re-fragment
            // re-fragment: acc -> bias+relu -> split-bf16 A frags (STS.128, CF)
            uint4* dAh = (uint4*)(smem + OFF_AHI);
            uint4* dAl = (uint4*)(smem + OFF_ALO);
            #pragma unroll
            for (int mi = 0; mi < 2; mi++) {
                int mt = (w & 3) * 2 + mi;
                #pragma unroll
                for (int j = 0; j < 4; j++) {
                    int s = (w >> 2) * 4 + j;
                    int colA = (w >> 2) * 64 + (2 * j) * 8 + tq * 2;
                    int colB = colA + 8;
                    float bA0 = bs[colA], bA1 = bs[colA + 1];
                    float bB0 = bs[colB], bB1 = bs[colB + 1];
                    uint4 hi, lo;
                    pack_hilo(fmaxf(acc[mi][2 * j][0] + bA0, 0.f),
                              fmaxf(acc[mi][2 * j][1] + bA1, 0.f), hi.x, lo.x);
                    pack_hilo(fmaxf(acc[mi][2 * j][2] + bA0, 0.f),
                              fmaxf(acc[mi][2 * j][3] + bA1, 0.f), hi.y, lo.y);
                    pack_hilo(fmaxf(acc[mi][2 * j + 1][0] + bB0, 0.f),
                              fmaxf(acc[mi][2 * j + 1][1] + bB1, 0.f), hi.z, lo.z);
                    pack_hilo(fmaxf(acc[mi][2 * j + 1][2] + bB0, 0.f),
                              fmaxf(acc[mi][2 * j + 1][3] + bB1, 0.f), hi.w, lo.w);
                    int idx = (s * 8 + mt) * 32 + lid;
                    dAh[idx] = hi;
                    dAl[idx] = lo;
                }
            }
            cp_wait0();
            __syncthreads();
        } else {
            // final: bias + relu, direct stores
            #pragma unroll
            for (int mi = 0; mi < 2; mi++)
                #pragma unroll
                for (int nt = 0; nt < 8; nt++) {
                    int col = (w >> 2) * 64 + nt * 8 + tq * 2;
                    float b0 = bs[col], b1 = bs[col + 1];
                    int r0 = row0 + (w & 3) * 32 + mi * 16 + g;
                    if (r0 < M)
                        *(float2*)(out + (size_t)r0 * HID + col) =
                            make_float2(fmaxf(acc[mi][nt][0] + b0, 0.f),
                                        fmaxf(acc[mi][nt][1] + b1, 0.f));
                    int r1 = r0 + 8;
                    if (r1 < M)
                        *(float2*)(out + (size_t)r1 * HID + col) =
                            make_float2(fmaxf(acc[mi][nt][2] + b0, 0.f),
                                        fmaxf(acc[mi][nt][3] + b1, 0.f));
                }
        }
    }
}

// ---------------------------------------------------------------------------
// Launch
// ---------------------------------------------------------------------------
extern "C" void kernel_launch(void* const* d_in, const int* in_sizes, int n_in,
                              void* d_out, int out_size)
{
    const float* x    = (const float*)d_in[0];
    const int*   ei   = (const int*)  d_in[1];
    const int*   ea   = (const int*)  d_in[2];
    const float* Wx   = (const float*)d_in[3];
    const float* bx   = (const float*)d_in[4];
    const float* emb  = (const float*)d_in[5];
    const float* eps1 = (const float*)d_in[6];
    const float* eps2 = (const float*)d_in[7];
    const float* W1a  = (const float*)d_in[8];
    const float* b1a  = (const float*)d_in[9];
    const float* W1b  = (const float*)d_in[10];
    const float* b1b  = (const float*)d_in[11];
    const float* W1c  = (const float*)d_in[12];
    const float* b1c  = (const float*)d_in[13];
    const float* W2a  = (const float*)d_in[14];
    const float* b2a  = (const float*)d_in[15];
    const float* W2b  = (const float*)d_in[16];
    const float* b2b  = (const float*)d_in[17];
    const float* W2c  = (const float*)d_in[18];
    const float* b2c  = (const float*)d_in[19];

    const int M = in_sizes[0] / HID;   // 100000
    const int E = in_sizes[1] / 2;     // 1600000
    float* out = (float*)d_out;

    float* h   = nullptr; cudaGetSymbolAddress((void**)&h,   g_h);
    float* agg = nullptr; cudaGetSymbolAddress((void**)&agg, g_agg);
    __nv_bfloat16* wimg = nullptr; cudaGetSymbolAddress((void**)&wimg, g_wimg);

    cudaFuncSetAttribute(gemm_enc_kernel,
                         cudaFuncAttributeMaxDynamicSharedMemorySize, SM_TOTAL);
    cudaFuncSetAttribute(mlp3_kernel,
                         cudaFuncAttributeMaxDynamicSharedMemorySize, SM_TOTAL);

    // single prep launch for all 7 weights
    prep_all_kernel<<<dim3(64, 7), 256>>>(Wx, W1a, W1b, W1c, W2a, W2b, W2c, wimg);

    const dim3 gemm_grid((M + 127) / 128);
    const int  n4 = M * HID / 4;
    const dim3 zero_grid((n4 + 255) / 256);
    const dim3 scat_grid((E + 7) / 8);
    auto WI = [&](int i) { return wimg + (size_t)i * 32768; };

    // Encode
    gemm_enc_kernel<<<gemm_grid, 256, SM_TOTAL>>>(x, WI(0), bx, h, M);

    // GINE layer 1
    zero_kernel<<<zero_grid, 256>>>((float4*)agg, n4);
    scatter_kernel<<<scat_grid, 256>>>(h, ei, ea, emb, agg, E);
    mlp3_kernel<<<gemm_grid, 256, SM_TOTAL>>>(h, agg, eps1, WI(1), WI(2), WI(3),
                                              b1a, b1b, b1c, h, M);

    // GINE layer 2
    zero_kernel<<<zero_grid, 256>>>((float4*)agg, n4);
    scatter_kernel<<<scat_grid, 256>>>(h, ei, ea, emb, agg, E);
    mlp3_kernel<<<gemm_grid, 256, SM_TOTAL>>>(h, agg, eps2, WI(4), WI(5), WI(6),
                                              b2a, b2b, b2c, out, M);
}

// round 5
// speedup vs baseline: 2.6042x; 1.6705x over previous
#include <cuda_runtime.h>
#include <cuda_bf16.h>
#include <cstdint>

constexpr int HID = 128;
constexpr int N_NODES_MAX = 100000;
constexpr int N_EDGES_MAX = 1600000;
constexpr int N_EDGE_TYPES = 8;

// Scratch (device globals: allocation-free)
__device__ float g_h[(size_t)N_NODES_MAX * HID];
__device__ float g_agg[(size_t)N_NODES_MAX * HID];
__device__ __nv_bfloat16 g_wimg[7 * 2 * 16384];
// CSR scratch
__device__ int g_deg[N_NODES_MAX];          // histogram, then reused as cursor
__device__ int g_off[N_NODES_MAX + 1];
__device__ int g_bsum[256];
__device__ int g_packed[N_EDGES_MAX];       // src | (etype << 20)

// ---------------------------------------------------------------------------
// helpers
// ---------------------------------------------------------------------------
__device__ __forceinline__ uint32_t smem_u32(const void* p) {
    uint32_t a;
    asm("{ .reg .u64 t; cvta.to.shared.u64 t, %1; cvt.u32.u64 %0, t; }" : "=r"(a) : "l"(p));
    return a;
}
__device__ __forceinline__ void cp_async16(uint32_t saddr, const void* g) {
    asm volatile("cp.async.cg.shared.global [%0], [%1], 16;" :: "r"(saddr), "l"(g) : "memory");
}
__device__ __forceinline__ void cp_commit() {
    asm volatile("cp.async.commit_group;" ::: "memory");
}
__device__ __forceinline__ void cp_wait0() {
    asm volatile("cp.async.wait_group 0;" ::: "memory");
}
__device__ __forceinline__ void mma_bf16(float* c, const uint4& a,
                                         uint32_t b0, uint32_t b1) {
    asm volatile(
        "mma.sync.aligned.m16n8k16.row.col.f32.bf16.bf16.f32 "
        "{%0,%1,%2,%3}, {%4,%5,%6,%7}, {%8,%9}, {%0,%1,%2,%3};"
        : "+f"(c[0]), "+f"(c[1]), "+f"(c[2]), "+f"(c[3])
        : "r"(a.x), "r"(a.y), "r"(a.z), "r"(a.w), "r"(b0), "r"(b1));
}
__device__ __forceinline__ void pack_hilo(float a, float b, uint32_t& hi, uint32_t& lo) {
    __nv_bfloat16 ha = __float2bfloat16_rn(a), hb = __float2bfloat16_rn(b);
    __nv_bfloat162 H(ha, hb);
    __nv_bfloat162 L(__float2bfloat16_rn(a - __bfloat162float(ha)),
                     __float2bfloat16_rn(b - __bfloat162float(hb)));
    hi = *(uint32_t*)&H;
    lo = *(uint32_t*)&L;
}

// smem layout (GEMM kernels)
constexpr int OFF_BIAS = 0;                 // 3 x 512 B
constexpr int OFF_AHI  = 2048;
constexpr int OFF_ALO  = OFF_AHI + 32768;
constexpr int OFF_BHI  = OFF_ALO + 32768;
constexpr int OFF_BLO  = OFF_BHI + 32768;
constexpr int SM_TOTAL = OFF_BLO + 32768;   // 133120

// ---------------------------------------------------------------------------
// Prep weights: split fp32 W into bf16 hi/lo in MMA B-fragment order
// ---------------------------------------------------------------------------
__global__ void prep_all_kernel(const float* W0, const float* W1, const float* W2,
                                const float* W3, const float* W4, const float* W5,
                                const float* W6, __nv_bfloat16* img) {
    const float* Ws[7] = {W0, W1, W2, W3, W4, W5, W6};
    int wi  = blockIdx.y;
    int idx = blockIdx.x * blockDim.x + threadIdx.x;
    if (idx >= 16384) return;
    int k = idx >> 7;
    int n = idx & 127;
    float w = Ws[wi][k * 128 + n];
    __nv_bfloat16 h = __float2bfloat16_rn(w);
    __nv_bfloat16 l = __float2bfloat16_rn(w - __bfloat162float(h));

    int s = k >> 4, half = (k & 15) >> 3, t = (k >> 1) & 3, e = k & 1;
    int g = n & 7, lane = g * 4 + t;
    int jt = n >> 3, jp = jt >> 1, which = jt & 1, reg = which * 2 + half;
    uint32_t off = (uint32_t)((s * 8 + jp) * 512 + lane * 16 + reg * 4 + e * 2);
    char* hi = (char*)(img + (size_t)wi * 32768);
    char* lo = hi + 32768;
    *(__nv_bfloat16*)(hi + off) = h;
    *(__nv_bfloat16*)(lo + off) = l;
}

// ---------------------------------------------------------------------------
// CSR build kernels
// ---------------------------------------------------------------------------
__global__ void zero_int_kernel(int* __restrict__ p, int n) {
    int i = blockIdx.x * blockDim.x + threadIdx.x;
    if (i < n) p[i] = 0;
}
__global__ void hist_kernel(const int* __restrict__ ei, int* __restrict__ deg, int E) {
    int e = blockIdx.x * blockDim.x + threadIdx.x;
    if (e >= E) return;
    atomicAdd(&deg[ei[E + e]], 1);
}
// Phase 1: per-block exclusive scan (2048 elems/block of 512 threads)
__global__ __launch_bounds__(512) void scan1_kernel(
    const int* __restrict__ deg, int* __restrict__ out, int* __restrict__ bsum, int M)
{
    __shared__ int warp_sums[16];
    int tid = threadIdx.x;
    int base = blockIdx.x * 2048 + tid * 4;
    int v[4];
    #pragma unroll
    for (int j = 0; j < 4; j++) v[j] = (base + j < M) ? deg[base + j] : 0;
    int t = v[0] + v[1] + v[2] + v[3];
    int lane = tid & 31, wid = tid >> 5;
    int x = t;
    #pragma unroll
    for (int o = 1; o < 32; o <<= 1) {
        int y = __shfl_up_sync(0xFFFFFFFFu, x, o);
        if (lane >= o) x += y;
    }
    if (lane == 31) warp_sums[wid] = x;
    __syncthreads();
    if (wid == 0 && lane < 16) {
        int s = warp_sums[lane];
        #pragma unroll
        for (int o = 1; o < 16; o <<= 1) {
            int y = __shfl_up_sync(0xFFFFu, s, o);
            if (lane >= o) s += y;
        }
        warp_sums[lane] = s;
    }
    __syncthreads();
    int warp_excl = (wid == 0) ? 0 : warp_sums[wid - 1];
    int run = warp_excl + (x - t);
    #pragma unroll
    for (int j = 0; j < 4; j++) {
        if (base + j < M) out[base + j] = run;
        run += v[j];
    }
    if (tid == 0) bsum[blockIdx.x] = warp_sums[15];
}
// Phase 2: scan block sums (single thread; nb <= 64)
__global__ void scan2_kernel(int* __restrict__ bsum, int nb) {
    int run = 0;
    for (int i = 0; i < nb; i++) { int v = bsum[i]; bsum[i] = run; run += v; }
}
// Phase 3: add block offsets; init cursor; set off[M]=E
__global__ __launch_bounds__(512) void scan3_kernel(
    int* __restrict__ off, int* __restrict__ cursor,
    const int* __restrict__ bsum, int M, int E)
{
    int base = blockIdx.x * 2048 + threadIdx.x * 4;
    int add = bsum[blockIdx.x];
    #pragma unroll
    for (int j = 0; j < 4; j++) {
        if (base + j < M) {
            int v = off[base + j] + add;
            off[base + j] = v;
            cursor[base + j] = v;
        }
    }
    if (blockIdx.x == 0 && threadIdx.x == 0) off[M] = E;
}
__global__ void fill_kernel(const int* __restrict__ ei, const int* __restrict__ et,
                            int* __restrict__ cursor, int* __restrict__ packed, int E)
{
    int e = blockIdx.x * blockDim.x + threadIdx.x;
    if (e >= E) return;
    int d = ei[E + e];
    int pos = atomicAdd(&cursor[d], 1);
    packed[pos] = ei[e] | (et[e] << 20);
}

// ---------------------------------------------------------------------------
// CSR aggregation: agg[n] = sum_{e in in(n)} relu(h[src_e] + emb[et_e])
// Warp per node; lane handles 4 feats; 2-edge unroll for MLP.
// ---------------------------------------------------------------------------
__global__ __launch_bounds__(256) void agg_kernel(
    const float* __restrict__ h, const int* __restrict__ packed,
    const int* __restrict__ off, const float* __restrict__ emb,
    float* __restrict__ agg, int M)
{
    __shared__ float semb[N_EDGE_TYPES * HID];
    for (int i = threadIdx.x; i < N_EDGE_TYPES * HID; i += 256) semb[i] = emb[i];
    __syncthreads();

    int n = blockIdx.x * 8 + (threadIdx.x >> 5);
    if (n >= M) return;
    int lane = threadIdx.x & 31;

    int beg = off[n], end = off[n + 1];
    float4 acc = make_float4(0.f, 0.f, 0.f, 0.f);
    int e = beg;
    for (; e + 2 <= end; e += 2) {
        int p0 = packed[e], p1 = packed[e + 1];
        float4 h0 = *(const float4*)(h + (size_t)(p0 & 0xFFFFF) * HID + lane * 4);
        float4 h1 = *(const float4*)(h + (size_t)(p1 & 0xFFFFF) * HID + lane * 4);
        float4 e0 = *(const float4*)(semb + (p0 >> 20) * HID + lane * 4);
        float4 e1 = *(const float4*)(semb + (p1 >> 20) * HID + lane * 4);
        acc.x += fmaxf(h0.x + e0.x, 0.f) + fmaxf(h1.x + e1.x, 0.f);
        acc.y += fmaxf(h0.y + e0.y, 0.f) + fmaxf(h1.y + e1.y, 0.f);
        acc.z += fmaxf(h0.z + e0.z, 0.f) + fmaxf(h1.z + e1.z, 0.f);
        acc.w += fmaxf(h0.w + e0.w, 0.f) + fmaxf(h1.w + e1.w, 0.f);
    }
    if (e < end) {
        int p0 = packed[e];
        float4 h0 = *(const float4*)(h + (size_t)(p0 & 0xFFFFF) * HID + lane * 4);
        float4 e0 = *(const float4*)(semb + (p0 >> 20) * HID + lane * 4);
        acc.x += fmaxf(h0.x + e0.x, 0.f);
        acc.y += fmaxf(h0.y + e0.y, 0.f);
        acc.z += fmaxf(h0.z + e0.z, 0.f);
        acc.w += fmaxf(h0.w + e0.w, 0.f);
    }
    *(float4*)(agg + (size_t)n * HID + lane * 4) = acc;
}

// ---------------------------------------------------------------------------
// GEMM machinery (unchanged from R4)
// ---------------------------------------------------------------------------
__device__ __forceinline__ void mma_mainloop(const char* smem, int w, int lid,
                                             float acc[2][8][4]) {
    const int mt0 = (w & 3) * 2;
    const int jp0 = (w >> 2) * 4;
    const uint4* sAh = (const uint4*)(smem + OFF_AHI);
    const uint4* sAl = (const uint4*)(smem + OFF_ALO);
    const uint4* sBh = (const uint4*)(smem + OFF_BHI);
    const uint4* sBl = (const uint4*)(smem + OFF_BLO);
    #pragma unroll
    for (int s = 0; s < 8; s++) {
        uint4 ah0 = sAh[(s * 8 + mt0) * 32 + lid];
        uint4 ah1 = sAh[(s * 8 + mt0 + 1) * 32 + lid];
        uint4 al0 = sAl[(s * 8 + mt0) * 32 + lid];
        uint4 al1 = sAl[(s * 8 + mt0 + 1) * 32 + lid];
        uint4 b[4];
        #pragma unroll
        for (int p = 0; p < 4; p++) b[p] = sBh[(s * 8 + jp0 + p) * 32 + lid];
        #pragma unroll
        for (int p = 0; p < 4; p++) {
            mma_bf16(acc[0][2 * p],     ah0, b[p].x, b[p].y);
            mma_bf16(acc[1][2 * p],     ah1, b[p].x, b[p].y);
            mma_bf16(acc[0][2 * p + 1], ah0, b[p].z, b[p].w);
            mma_bf16(acc[1][2 * p + 1], ah1, b[p].z, b[p].w);
            mma_bf16(acc[0][2 * p],     al0, b[p].x, b[p].y);
            mma_bf16(acc[1][2 * p],     al1, b[p].x, b[p].y);
            mma_bf16(acc[0][2 * p + 1], al0, b[p].z, b[p].w);
            mma_bf16(acc[1][2 * p + 1], al1, b[p].z, b[p].w);
        }
        #pragma unroll
        for (int p = 0; p < 4; p++) b[p] = sBl[(s * 8 + jp0 + p) * 32 + lid];
        #pragma unroll
        for (int p = 0; p < 4; p++) {
            mma_bf16(acc[0][2 * p],     ah0, b[p].x, b[p].y);
            mma_bf16(acc[1][2 * p],     ah1, b[p].x, b[p].y);
            mma_bf16(acc[0][2 * p + 1], ah0, b[p].z, b[p].w);
            mma_bf16(acc[1][2 * p + 1], ah1, b[p].z, b[p].w);
        }
    }
}

__device__ __forceinline__ void load_B_async(char* smem, const __nv_bfloat16* wimg,
                                             int tid) {
    uint32_t hB = smem_u32(smem + OFF_BHI);
    uint32_t lB = smem_u32(smem + OFF_BLO);
    const uint4* hs = (const uint4*)wimg;
    const uint4* ls = (const uint4*)(wimg + 16384);
    #pragma unroll
    for (int i = tid; i < 2048; i += 256) {
        cp_async16(hB + i * 16, hs + i);
        cp_async16(lB + i * 16, ls + i);
    }
    cp_commit();
}

template<bool COMBINE>
__device__ __forceinline__ void convert_A(char* smem, const float* A, const float* B,
                                          float e, int row0, int M, int tid) {
    #pragma unroll
    for (int i = tid; i < 4096; i += 256) {
        int row = i >> 5;
        int k0  = (i & 31) * 4;
        int gr  = row0 + row;
        float4 v = make_float4(0.f, 0.f, 0.f, 0.f);
        if (gr < M) {
            v = *(const float4*)(A + (size_t)gr * HID + k0);
            if (COMBINE) {
                float4 b = *(const float4*)(B + (size_t)gr * HID + k0);
                v.x = fmaf(e, v.x, b.x); v.y = fmaf(e, v.y, b.y);
                v.z = fmaf(e, v.z, b.z); v.w = fmaf(e, v.w, b.w);
            }
        }
        uint32_t h01, l01, h23, l23;
        pack_hilo(v.x, v.y, h01, l01);
        pack_hilo(v.z, v.w, h23, l23);
        int s    = k0 >> 4;
        int half = (k0 >> 3) & 1;
        int t    = (k0 >> 1) & 3;
        int g    = row & 7;
        int rbit = (row >> 3) & 1;
        int mt   = row >> 4;
        int r    = rbit + 2 * half;
        uint32_t base = (uint32_t)((s * 8 + mt) * 512 + (g * 4 + t) * 16 + r * 4);
        *(uint32_t*)(smem + OFF_AHI + base)      = h01;
        *(uint32_t*)(smem + OFF_AHI + base + 16) = h23;
        *(uint32_t*)(smem + OFF_ALO + base)      = l01;
        *(uint32_t*)(smem + OFF_ALO + base + 16) = l23;
    }
}

__global__ __launch_bounds__(256) void gemm_enc_kernel(
    const float* __restrict__ A,
    const __nv_bfloat16* __restrict__ wimg,
    const float* __restrict__ bias,
    float* __restrict__ out, int M)
{
    extern __shared__ char smem[];
    const int tid = threadIdx.x, w = tid >> 5, lid = tid & 31;
    const int row0 = blockIdx.x * 128;

    load_B_async(smem, wimg, tid);
    if (tid < 128) *(float*)(smem + OFF_BIAS + tid * 4) = bias[tid];
    convert_A<false>(smem, A, nullptr, 0.f, row0, M, tid);
    cp_wait0();
    __syncthreads();

    float acc[2][8][4];
    #pragma unroll
    for (int mi = 0; mi < 2; mi++)
        #pragma unroll
        for (int nt = 0; nt < 8; nt++)
            #pragma unroll
            for (int c = 0; c < 4; c++) acc[mi][nt][c] = 0.f;

    mma_mainloop(smem, w, lid, acc);

    const int g = lid >> 2, tq = lid & 3;
    const float* bs = (const float*)(smem + OFF_BIAS);
    #pragma unroll
    for (int mi = 0; mi < 2; mi++)
        #pragma unroll
        for (int nt = 0; nt < 8; nt++) {
            int col = (w >> 2) * 64 + nt * 8 + tq * 2;
            float b0 = bs[col], b1 = bs[col + 1];
            int r0 = row0 + (w & 3) * 32 + mi * 16 + g;
            if (r0 < M)
                *(float2*)(out + (size_t)r0 * HID + col) =
                    make_float2(fmaxf(acc[mi][nt][0] + b0, 0.f),
                                fmaxf(acc[mi][nt][1] + b1, 0.f));
            int r1 = r0 + 8;
            if (r1 < M)
                *(float2*)(out + (size_t)r1 * HID + col) =
                    make_float2(fmaxf(acc[mi][nt][2] + b0, 0.f),
                                fmaxf(acc[mi][nt][3] + b1, 0.f));
        }
}

__global__ __launch_bounds__(256) void mlp3_kernel(
    const float* __restrict__ A,
    const float* __restrict__ B,
    const float* __restrict__ eps,
    const __nv_bfloat16* __restrict__ wa,
    const __nv_bfloat16* __restrict__ wb,
    const __nv_bfloat16* __restrict__ wc,
    const float* __restrict__ ba,
    const float* __restrict__ bb,
    const float* __restrict__ bc,
    float* __restrict__ out, int M)
{
    extern __shared__ char smem[];
    const int tid = threadIdx.x, w = tid >> 5, lid = tid & 31;
    const int row0 = blockIdx.x * 128;
    const float e = 1.0f + eps[0];

    load_B_async(smem, wa, tid);
    if (tid < 128) {
        *(float*)(smem + OFF_BIAS +        tid * 4) = ba[tid];
        *(float*)(smem + OFF_BIAS +  512 + tid * 4) = bb[tid];
        *(float*)(smem + OFF_BIAS + 1024 + tid * 4) = bc[tid];
    }
    convert_A<true>(smem, A, B, e, row0, M, tid);
    cp_wait0();
    __syncthreads();

    float acc[2][8][4];
    const int g = lid >> 2, tq = lid & 3;
    const __nv_bfloat16* next_w[2] = {wb, wc};

    #pragma unroll
    for (int st = 0; st < 3; st++) {
        #pragma unroll
        for (int mi = 0; mi < 2; mi++)
            #pragma unroll
            for (int nt = 0; nt < 8; nt++)
                #pragma unroll
                for (int c = 0; c < 4; c++) acc[mi][nt][c] = 0.f;

        mma_mainloop(smem, w, lid, acc);
        __syncthreads();

        const float* bs = (const float*)(smem + OFF_BIAS + st * 512);

        if (st < 2) {
            load_B_async(smem, next_w[st], tid);
            uint4* dAh = (uint4*)(smem + OFF_AHI);
            uint4* dAl = (uint4*)(smem + OFF_ALO);
            #pragma unroll
            for (int mi = 0; mi < 2; mi++) {
                int mt = (w & 3) * 2 + mi;
                #pragma unroll
                for (int j = 0; j < 4; j++) {
                    int s = (w >> 2) * 4 + j;
                    int colA = (w >> 2) * 64 + (2 * j) * 8 + tq * 2;
                    int colB = colA + 8;
                    float bA0 = bs[colA], bA1 = bs[colA + 1];
                    float bB0 = bs[colB], bB1 = bs[colB + 1];
                    uint4 hi, lo;
                    pack_hilo(fmaxf(acc[mi][2 * j][0] + bA0, 0.f),
                              fmaxf(acc[mi][2 * j][1] + bA1, 0.f), hi.x, lo.x);
                    pack_hilo(fmaxf(acc[mi][2 * j][2] + bA0, 0.f),
                              fmaxf(acc[mi][2 * j][3] + bA1, 0.f), hi.y, lo.y);
                    pack_hilo(fmaxf(acc[mi][2 * j + 1][0] + bB0, 0.f),
                              fmaxf(acc[mi][2 * j + 1][1] + bB1, 0.f), hi.z, lo.z);
                    pack_hilo(fmaxf(acc[mi][2 * j + 1][2] + bB0, 0.f),
                              fmaxf(acc[mi][2 * j + 1][3] + bB1, 0.f), hi.w, lo.w);
                    int idx = (s * 8 + mt) * 32 + lid;
                    dAh[idx] = hi;
                    dAl[idx] = lo;
                }
            }
            cp_wait0();
            __syncthreads();
        } else {
            #pragma unroll
            for (int mi = 0; mi < 2; mi++)
                #pragma unroll
                for (int nt = 0; nt < 8; nt++) {
                    int col = (w >> 2) * 64 + nt * 8 + tq * 2;
                    float b0 = bs[col], b1 = bs[col + 1];
                    int r0 = row0 + (w & 3) * 32 + mi * 16 + g;
                    if (r0 < M)
                        *(float2*)(out + (size_t)r0 * HID + col) =
                            make_float2(fmaxf(acc[mi][nt][0] + b0, 0.f),
                                        fmaxf(acc[mi][nt][1] + b1, 0.f));
                    int r1 = r0 + 8;
                    if (r1 < M)
                        *(float2*)(out + (size_t)r1 * HID + col) =
                            make_float2(fmaxf(acc[mi][nt][2] + b0, 0.f),
                                        fmaxf(acc[mi][nt][3] + b1, 0.f));
                }
        }
    }
}

// ---------------------------------------------------------------------------
// Launch
// ---------------------------------------------------------------------------
extern "C" void kernel_launch(void* const* d_in, const int* in_sizes, int n_in,
                              void* d_out, int out_size)
{
    const float* x    = (const float*)d_in[0];
    const int*   ei   = (const int*)  d_in[1];
    const int*   ea   = (const int*)  d_in[2];
    const float* Wx   = (const float*)d_in[3];
    const float* bx   = (const float*)d_in[4];
    const float* emb  = (const float*)d_in[5];
    const float* eps1 = (const float*)d_in[6];
    const float* eps2 = (const float*)d_in[7];
    const float* W1a  = (const float*)d_in[8];
    const float* b1a  = (const float*)d_in[9];
    const float* W1b  = (const float*)d_in[10];
    const float* b1b  = (const float*)d_in[11];
    const float* W1c  = (const float*)d_in[12];
    const float* b1c  = (const float*)d_in[13];
    const float* W2a  = (const float*)d_in[14];
    const float* b2a  = (const float*)d_in[15];
    const float* W2b  = (const float*)d_in[16];
    const float* b2b  = (const float*)d_in[17];
    const float* W2c  = (const float*)d_in[18];
    const float* b2c  = (const float*)d_in[19];

    const int M = in_sizes[0] / HID;   // 100000
    const int E = in_sizes[1] / 2;     // 1600000
    float* out = (float*)d_out;

    float* h    = nullptr; cudaGetSymbolAddress((void**)&h,    g_h);
    float* agg  = nullptr; cudaGetSymbolAddress((void**)&agg,  g_agg);
    __nv_bfloat16* wimg = nullptr; cudaGetSymbolAddress((void**)&wimg, g_wimg);
    int* deg    = nullptr; cudaGetSymbolAddress((void**)&deg,    g_deg);
    int* off    = nullptr; cudaGetSymbolAddress((void**)&off,    g_off);
    int* bsum   = nullptr; cudaGetSymbolAddress((void**)&bsum,   g_bsum);
    int* packed = nullptr; cudaGetSymbolAddress((void**)&packed, g_packed);

    cudaFuncSetAttribute(gemm_enc_kernel,
                         cudaFuncAttributeMaxDynamicSharedMemorySize, SM_TOTAL);
    cudaFuncSetAttribute(mlp3_kernel,
                         cudaFuncAttributeMaxDynamicSharedMemorySize, SM_TOTAL);

    prep_all_kernel<<<dim3(64, 7), 256>>>(Wx, W1a, W1b, W1c, W2a, W2b, W2c, wimg);

    // ---- build CSR (dst-sorted, once per launch) ----
    const int nb = (M + 2047) / 2048;
    zero_int_kernel<<<(M + 255) / 256, 256>>>(deg, M);
    hist_kernel<<<(E + 255) / 256, 256>>>(ei, deg, E);
    scan1_kernel<<<nb, 512>>>(deg, off, bsum, M);
    scan2_kernel<<<1, 1>>>(bsum, nb);
    scan3_kernel<<<nb, 512>>>(off, deg, bsum, M, E);   // deg reused as cursor
    fill_kernel<<<(E + 255) / 256, 256>>>(ei, ea, deg, packed, E);

    const dim3 gemm_grid((M + 127) / 128);
    const dim3 agg_grid((M + 7) / 8);
    auto WI = [&](int i) { return wimg + (size_t)i * 32768; };

    // Encode
    gemm_enc_kernel<<<gemm_grid, 256, SM_TOTAL>>>(x, WI(0), bx, h, M);

    // GINE layer 1
    agg_kernel<<<agg_grid, 256>>>(h, packed, off, emb, agg, M);
    mlp3_kernel<<<gemm_grid, 256, SM_TOTAL>>>(h, agg, eps1, WI(1), WI(2), WI(3),
                                              b1a, b1b, b1c, h, M);

    // GINE layer 2
    agg_kernel<<<agg_grid, 256>>>(h, packed, off, emb, agg, M);
    mlp3_kernel<<<gemm_grid, 256, SM_TOTAL>>>(h, agg, eps2, WI(4), WI(5), WI(6),
                                              b2a, b2b, b2c, out, M);
}